// round 15
// baseline (speedup 1.0000x reference)
#include <cuda_runtime.h>
#include <cuda_bf16.h>
#include <cstdint>

#define NNODES 50000
#define NEDGES 150000
#define EPLUS  (NEDGES + NNODES)   // edges + self loops = 200000
#define NGRAPH 1024
#define INDIM  78
#define KP1    128                 // layer-1 K padded to 128
#define HID    640
#define HEADS  10
#define C1     64
#define NEGSLOPE 0.2f

// ---------------- scratch (static __device__ — no allocations allowed) -----
__device__ __align__(128) float g_bufA[(size_t)NNODES * HID];
__device__ __align__(128) float g_bufB[(size_t)NNODES * HID];
__device__ float g_dinv[NNODES];
__device__ int   g_rowptr[NNODES + 1];
__device__ int   g_cntbuf[2 * NNODES];      // [0,N) count, [N,2N) scatter-fill
__device__ int   g_csr_src[EPLUS];
__device__ int   g_gmax[NGRAPH * HID];
__device__ float g_gsum[NGRAPH * HID];
__device__ float g_cnt [NGRAPH];
// bf16 split buffers
__device__ __align__(128) __nv_bfloat16 g_xhi[(size_t)NNODES * KP1];
__device__ __align__(128) __nv_bfloat16 g_xlo[(size_t)NNODES * KP1];
__device__ __align__(128) __nv_bfloat16 g_hhi[(size_t)NNODES * HID];
__device__ __align__(128) __nv_bfloat16 g_hlo[(size_t)NNODES * HID];
__device__ __align__(128) __nv_bfloat16 g_w1lhi[HID * KP1], g_w1llo[HID * KP1];
__device__ __align__(128) __nv_bfloat16 g_w1rhi[HID * KP1], g_w1rlo[HID * KP1];
__device__ __align__(128) __nv_bfloat16 g_w2lhi[HID * HID], g_w2llo[HID * HID];
__device__ __align__(128) __nv_bfloat16 g_w2rhi[HID * HID], g_w2rlo[HID * HID];
__device__ __align__(128) __nv_bfloat16 g_wghi [HID * HID], g_wglo [HID * HID];

// ---------------- helpers --------------------------------------------------
__device__ __forceinline__ uint32_t smem_u32(const void* p) {
    return (uint32_t)__cvta_generic_to_shared(p);
}
#define LDSM4(r0, r1, r2, r3, addr) \
    asm volatile("ldmatrix.sync.aligned.m8n8.x4.shared.b16 {%0,%1,%2,%3}, [%4];" \
                 : "=r"(r0), "=r"(r1), "=r"(r2), "=r"(r3) : "r"(addr))
#define MMA16816(c, a0, a1, a2, a3, b0, b1) \
    asm volatile("mma.sync.aligned.m16n8k16.row.col.f32.bf16.bf16.f32 " \
                 "{%0,%1,%2,%3}, {%4,%5,%6,%7}, {%8,%9}, {%0,%1,%2,%3};" \
                 : "+f"((c)[0]), "+f"((c)[1]), "+f"((c)[2]), "+f"((c)[3]) \
                 : "r"(a0), "r"(a1), "r"(a2), "r"(a3), "r"(b0), "r"(b1))
__device__ __forceinline__ void cpasync16(uint32_t dst, const void* src, int sz) {
    asm volatile("cp.async.cg.shared.global [%0], [%1], 16, %2;"
                 :: "r"(dst), "l"(src), "r"(sz));
}
#define CP_COMMIT asm volatile("cp.async.commit_group;")
#define CP_WAIT1  asm volatile("cp.async.wait_group 1;")
#define CP_WAIT0  asm volatile("cp.async.wait_group 0;")

// ---------------- fills ----------------------------------------------------
__global__ void k_fill_i(int* p, int v, int n) {
    int i = blockIdx.x * blockDim.x + threadIdx.x;
    if (i < n) p[i] = v;
}
__global__ void k_pool_init(int* __restrict__ gmax, float* __restrict__ gsum,
                            float* __restrict__ cnt) {
    int i = blockIdx.x * blockDim.x + threadIdx.x;
    if (i < NGRAPH * HID) { gmax[i] = 0; gsum[i] = 0.f; }
    if (i < NGRAPH) cnt[i] = 0.f;
}

// ---------------- CSR build ------------------------------------------------
__global__ void k_count(const int* __restrict__ ei, int* __restrict__ cnt) {
    int e = blockIdx.x * blockDim.x + threadIdx.x;
    if (e >= EPLUS) return;
    int d = (e < NEDGES) ? ei[NEDGES + e] : e - NEDGES;
    atomicAdd(&cnt[d], 1);
}
__global__ void k_scan(const int* __restrict__ cnt, int* __restrict__ rowptr) {
    __shared__ int sh[1024];
    __shared__ int carry;
    if (threadIdx.x == 0) carry = 0;
    __syncthreads();
    for (int base = 0; base < NNODES; base += 1024) {
        int i = base + threadIdx.x;
        int v = (i < NNODES) ? cnt[i] : 0;
        sh[threadIdx.x] = v;
        __syncthreads();
        for (int off = 1; off < 1024; off <<= 1) {
            int t = (threadIdx.x >= off) ? sh[threadIdx.x - off] : 0;
            __syncthreads();
            sh[threadIdx.x] += t;
            __syncthreads();
        }
        if (i < NNODES) rowptr[i] = carry + sh[threadIdx.x] - v;
        __syncthreads();
        if (threadIdx.x == 1023) carry += sh[1023];
        __syncthreads();
    }
    if (threadIdx.x == 0) rowptr[NNODES] = EPLUS;
}
__global__ void k_scatter(const int* __restrict__ ei, const int* __restrict__ rowptr,
                          int* __restrict__ fill, int* __restrict__ csr_src) {
    int e = blockIdx.x * blockDim.x + threadIdx.x;
    if (e >= EPLUS) return;
    int s, d;
    if (e < NEDGES) { s = ei[e]; d = ei[NEDGES + e]; }
    else            { s = d = e - NEDGES; }
    int pos = rowptr[d] + atomicAdd(&fill[d], 1);
    csr_src[pos] = s;
}
__global__ void k_dinv(const int* __restrict__ rowptr, float* __restrict__ dinv) {
    int n = blockIdx.x * blockDim.x + threadIdx.x;
    if (n >= NNODES) return;
    dinv[n] = rsqrtf((float)(rowptr[n + 1] - rowptr[n]));   // >=1 (self loop)
}

// ---------------- bf16 hi/lo split prep ------------------------------------
__global__ void k_split(const float* __restrict__ src,
                        __nv_bfloat16* __restrict__ hi, __nv_bfloat16* __restrict__ lo,
                        int M, int K, int Kp)
{
    int idx = blockIdx.x * blockDim.x + threadIdx.x;
    if (idx >= M * Kp) return;
    int r = idx / Kp, k = idx - r * Kp;
    float v = (k < K) ? src[(size_t)r * K + k] : 0.f;
    __nv_bfloat16 h = __float2bfloat16(v);
    hi[idx] = h;
    lo[idx] = __float2bfloat16(v - __bfloat162float(h));
}
__global__ void k_splitT(const float* __restrict__ W,
                         __nv_bfloat16* __restrict__ hi, __nv_bfloat16* __restrict__ lo,
                         int K, int N, int Kp)
{
    int idx = blockIdx.x * blockDim.x + threadIdx.x;
    if (idx >= N * Kp) return;
    int n = idx / Kp, k = idx - n * Kp;
    float v = (k < K) ? W[(size_t)k * N + n] : 0.f;
    __nv_bfloat16 h = __float2bfloat16(v);
    hi[idx] = h;
    lo[idx] = __float2bfloat16(v - __bfloat162float(h));
}

// ---------------- split-bf16 HMMA GEMM, cp.async double buffer -------------
#define STG_T   10240               // bytes per tensor per stage (128*80)
#define STG_ALL 40960               // bytes per stage

__global__ __launch_bounds__(256, 2)
void k_hgemm(const __nv_bfloat16* __restrict__ Ahi, const __nv_bfloat16* __restrict__ Alo,
             const __nv_bfloat16* __restrict__ Bhi, const __nv_bfloat16* __restrict__ Blo,
             float* __restrict__ C, int M, int N, int K)
{
    extern __shared__ __align__(128) char smem[];
    const uint32_t sb = smem_u32(smem);
    const int tid = threadIdx.x, lane = tid & 31, wid = tid >> 5;
    const int wm = wid & 3, wn = wid >> 2;
    const int bm = blockIdx.y * 128, bn = blockIdx.x * 128;

    float c[2][8][4];
    #pragma unroll
    for (int i = 0; i < 2; i++)
        #pragma unroll
        for (int j = 0; j < 8; j++)
            #pragma unroll
            for (int q = 0; q < 4; q++) c[i][j][q] = 0.f;

    const int row = tid >> 1, half = tid & 1;
    const bool va = (bm + row) < M;
    const int szA = va ? 16 : 0;
    const char* gAh = (const char*)(Ahi + (size_t)(bm + row) * K) + half * 32;
    const char* gAl = (const char*)(Alo + (size_t)(bm + row) * K) + half * 32;
    const char* gBh = (const char*)(Bhi + (size_t)(bn + row) * K) + half * 32;
    const char* gBl = (const char*)(Blo + (size_t)(bn + row) * K) + half * 32;
    const uint32_t dOff = (uint32_t)(row * 80 + half * 32);

#define LOAD_STAGE(s, k0) do {                                              \
        uint32_t b_ = sb + (uint32_t)((s) & 1) * STG_ALL;                   \
        size_t kb_ = (size_t)(k0) * 2;                                      \
        cpasync16(b_ + 0 * STG_T + dOff,      gAh + kb_,      szA);         \
        cpasync16(b_ + 0 * STG_T + dOff + 16, gAh + kb_ + 16, szA);         \
        cpasync16(b_ + 1 * STG_T + dOff,      gAl + kb_,      szA);         \
        cpasync16(b_ + 1 * STG_T + dOff + 16, gAl + kb_ + 16, szA);         \
        cpasync16(b_ + 2 * STG_T + dOff,      gBh + kb_,      16);          \
        cpasync16(b_ + 2 * STG_T + dOff + 16, gBh + kb_ + 16, 16);          \
        cpasync16(b_ + 3 * STG_T + dOff,      gBl + kb_,      16);          \
        cpasync16(b_ + 3 * STG_T + dOff + 16, gBl + kb_ + 16, 16);          \
    } while (0)

    const uint32_t a_mr = (lane & 7) + ((lane >> 3) & 1) * 8;
    const uint32_t a_kc = (lane >> 4) * 8;
    const uint32_t b_nr = ((lane >> 4) & 1) * 8 + (lane & 7);
    const uint32_t b_kc = ((lane >> 3) & 1) * 8;

    const int nst = K >> 5;
    LOAD_STAGE(0, 0);
    CP_COMMIT;
    for (int s = 0; s < nst; s++) {
        if (s + 1 < nst) { LOAD_STAGE(s + 1, (s + 1) << 5); CP_COMMIT; CP_WAIT1; }
        else             { CP_WAIT0; }
        __syncthreads();

        uint32_t base = sb + (uint32_t)(s & 1) * STG_ALL;
        #pragma unroll
        for (int ksub = 0; ksub < 2; ksub++) {
            uint32_t ko = ksub * 32;
            uint32_t ah[2][4], al[2][4];
            #pragma unroll
            for (int mt = 0; mt < 2; mt++) {
                uint32_t aaddr = (uint32_t)((wm * 32 + mt * 16 + a_mr) * 80) + ko + a_kc * 2;
                LDSM4(ah[mt][0], ah[mt][1], ah[mt][2], ah[mt][3], base + 0 * STG_T + aaddr);
                LDSM4(al[mt][0], al[mt][1], al[mt][2], al[mt][3], base + 1 * STG_T + aaddr);
            }
            #pragma unroll
            for (int bg = 0; bg < 4; bg++) {
                uint32_t baddr = (uint32_t)((wn * 64 + bg * 16 + b_nr) * 80) + ko + b_kc * 2;
                uint32_t bh0, bh1, bh2, bh3, bl0, bl1, bl2, bl3;
                LDSM4(bh0, bh1, bh2, bh3, base + 2 * STG_T + baddr);
                LDSM4(bl0, bl1, bl2, bl3, base + 3 * STG_T + baddr);
                #pragma unroll
                for (int mt = 0; mt < 2; mt++) {
                    float* c0 = c[mt][bg * 2];
                    float* c1 = c[mt][bg * 2 + 1];
                    MMA16816(c0, ah[mt][0], ah[mt][1], ah[mt][2], ah[mt][3], bh0, bh1);
                    MMA16816(c0, ah[mt][0], ah[mt][1], ah[mt][2], ah[mt][3], bl0, bl1);
                    MMA16816(c0, al[mt][0], al[mt][1], al[mt][2], al[mt][3], bh0, bh1);
                    MMA16816(c1, ah[mt][0], ah[mt][1], ah[mt][2], ah[mt][3], bh2, bh3);
                    MMA16816(c1, ah[mt][0], ah[mt][1], ah[mt][2], ah[mt][3], bl2, bl3);
                    MMA16816(c1, al[mt][0], al[mt][1], al[mt][2], al[mt][3], bh2, bh3);
                }
            }
        }
        __syncthreads();
    }
#undef LOAD_STAGE

    const int rbase = bm + wm * 32 + (lane >> 2);
    const int cbase = bn + wn * 64 + (lane & 3) * 2;
    #pragma unroll
    for (int mt = 0; mt < 2; mt++) {
        #pragma unroll
        for (int nt = 0; nt < 8; nt++) {
            int rr = rbase + mt * 16;
            int cc = cbase + nt * 8;
            if (rr < M)
                *(float2*)&C[(size_t)rr * N + cc] = make_float2(c[mt][nt][0], c[mt][nt][1]);
            if (rr + 8 < M)
                *(float2*)&C[(size_t)(rr + 8) * N + cc] = make_float2(c[mt][nt][2], c[mt][nt][3]);
        }
    }
}

// ---------------- fused GATv2 layer 1 (H=10, C=64), warp per node ----------
// Chunked two-sweep softmax: sweep A gathers xl rows (DRAM) -> logits in
// lane-distributed regs; chunk-level rescale (exact softmax); sweep B
// re-gathers the same rows (L2-hot) for the weighted sum. Per-head (m,den)
// carried in 5 half-uniform registers (channel head = 2j + (lane>=16)).
__global__ void k_gat1_fused(const float* __restrict__ xl,
                             const float* __restrict__ xr,
                             const int* __restrict__ rowptr,
                             const int* __restrict__ csr_src,
                             const float* __restrict__ att,
                             const float* __restrict__ bias,
                             __nv_bfloat16* __restrict__ ohi,
                             __nv_bfloat16* __restrict__ olo)
{
    int n = (blockIdx.x * blockDim.x + threadIdx.x) >> 5;
    int lane = threadIdx.x & 31;
    if (n >= NNODES) return;
    int r0 = rowptr[n], r1 = rowptr[n + 1];
    int k16 = lane & 15;

    float4 xr4[5], at4[5];
    const float4* pr = (const float4*)(xr + (size_t)n * HID);
    const float4* pa = (const float4*)att;
    #pragma unroll
    for (int j = 0; j < 5; j++) {
        xr4[j] = pr[j * 32 + lane];
        at4[j] = pa[j * 32 + lane];
    }

    float m[5], den[5], acc[5][4];
    #pragma unroll
    for (int j = 0; j < 5; j++) {
        m[j] = -3.4e38f; den[j] = 0.f;
        acc[j][0] = acc[j][1] = acc[j][2] = acc[j][3] = 0.f;
    }

    for (int cs = r0; cs < r1; cs += 16) {
        int ce = min(cs + 16, r1);
        float logreg[5];
        float cmax[5];
        #pragma unroll
        for (int j = 0; j < 5; j++) cmax[j] = -3.4e38f;

        // sweep A: logits (full-warp gather + 16-lane half reductions)
        for (int i = cs; i < ce; i++) {
            int s = csr_src[i];
            const float4* ps = (const float4*)(xl + (size_t)s * HID);
            float part[5];
            #pragma unroll
            for (int j = 0; j < 5; j++) {
                float4 x4 = ps[j * 32 + lane];
                float v, sum = 0.f;
                v = x4.x + xr4[j].x; v = v > 0.f ? v : NEGSLOPE * v; sum += v * at4[j].x;
                v = x4.y + xr4[j].y; v = v > 0.f ? v : NEGSLOPE * v; sum += v * at4[j].y;
                v = x4.z + xr4[j].z; v = v > 0.f ? v : NEGSLOPE * v; sum += v * at4[j].z;
                v = x4.w + xr4[j].w; v = v > 0.f ? v : NEGSLOPE * v; sum += v * at4[j].w;
                part[j] = sum;
            }
            #pragma unroll
            for (int o = 8; o > 0; o >>= 1) {
                #pragma unroll
                for (int j = 0; j < 5; j++)
                    part[j] += __shfl_xor_sync(0xffffffffu, part[j], o);
            }
            int k = i - cs;
            #pragma unroll
            for (int j = 0; j < 5; j++) {
                if (k16 == k) logreg[j] = part[j];
                cmax[j] = fmaxf(cmax[j], part[j]);
            }
        }
        // chunk rescale (exact: one rescale per chunk)
        #pragma unroll
        for (int j = 0; j < 5; j++) {
            float nm = fmaxf(m[j], cmax[j]);
            float sc = expf(m[j] - nm);
            den[j] *= sc;
            acc[j][0] *= sc; acc[j][1] *= sc; acc[j][2] *= sc; acc[j][3] *= sc;
            m[j] = nm;
        }
        // sweep B: weighted aggregate (rows L2-hot from sweep A)
        for (int i = cs; i < ce; i++) {
            int s = csr_src[i];
            const float4* ps = (const float4*)(xl + (size_t)s * HID);
            int srcl = (lane & 16) | (i - cs);
            #pragma unroll
            for (int j = 0; j < 5; j++) {
                float lg = __shfl_sync(0xffffffffu, logreg[j], srcl);
                float ex = expf(lg - m[j]);
                den[j] += ex;
                float4 x4 = ps[j * 32 + lane];
                acc[j][0] += ex * x4.x;
                acc[j][1] += ex * x4.y;
                acc[j][2] += ex * x4.z;
                acc[j][3] += ex * x4.w;
            }
        }
    }
    // finalize: bias + ELU + bf16 hi/lo split
    #pragma unroll
    for (int j = 0; j < 5; j++) {
        float inv = 1.f / den[j];
        int cb = (j * 32 + lane) * 4;
        float o0 = acc[j][0] * inv + bias[cb];
        float o1 = acc[j][1] * inv + bias[cb + 1];
        float o2 = acc[j][2] * inv + bias[cb + 2];
        float o3 = acc[j][3] * inv + bias[cb + 3];
        o0 = o0 > 0.f ? o0 : expm1f(o0);
        o1 = o1 > 0.f ? o1 : expm1f(o1);
        o2 = o2 > 0.f ? o2 : expm1f(o2);
        o3 = o3 > 0.f ? o3 : expm1f(o3);
        __nv_bfloat16 h0 = __float2bfloat16(o0), h1 = __float2bfloat16(o1);
        __nv_bfloat16 h2 = __float2bfloat16(o2), h3 = __float2bfloat16(o3);
        __nv_bfloat162 hp0; hp0.x = h0; hp0.y = h1;
        __nv_bfloat162 hp1; hp1.x = h2; hp1.y = h3;
        __nv_bfloat162 lp0, lp1;
        lp0.x = __float2bfloat16(o0 - __bfloat162float(h0));
        lp0.y = __float2bfloat16(o1 - __bfloat162float(h1));
        lp1.x = __float2bfloat16(o2 - __bfloat162float(h2));
        lp1.y = __float2bfloat16(o3 - __bfloat162float(h3));
        *(__nv_bfloat162*)&ohi[(size_t)n * HID + cb]     = hp0;
        *(__nv_bfloat162*)&ohi[(size_t)n * HID + cb + 2] = hp1;
        *(__nv_bfloat162*)&olo[(size_t)n * HID + cb]     = lp0;
        *(__nv_bfloat162*)&olo[(size_t)n * HID + cb + 2] = lp1;
    }
}

// ---------------- fused GATv2 layer 2 (H=1, C=640), warp per node ----------
__global__ void k_gat2_fused(const float* __restrict__ xl,
                             const float* __restrict__ xr,
                             const int* __restrict__ rowptr,
                             const int* __restrict__ csr_src,
                             const float* __restrict__ att,
                             const float* __restrict__ bias,
                             __nv_bfloat16* __restrict__ ohi,
                             __nv_bfloat16* __restrict__ olo)
{
    int n = (blockIdx.x * blockDim.x + threadIdx.x) >> 5;
    int lane = threadIdx.x & 31;
    if (n >= NNODES) return;
    int r0 = rowptr[n], r1 = rowptr[n + 1];

    float4 xr4[5], at4[5];
    const float4* pr = (const float4*)(xr + (size_t)n * HID);
    const float4* pa = (const float4*)att;
    #pragma unroll
    for (int j = 0; j < 5; j++) {
        xr4[j] = pr[j * 32 + lane];
        at4[j] = pa[j * 32 + lane];
    }

    float m = -3.4e38f, den = 0.f;
    float acc[5][4];
    #pragma unroll
    for (int j = 0; j < 5; j++)
        #pragma unroll
        for (int q = 0; q < 4; q++) acc[j][q] = 0.f;

    for (int cs = r0; cs < r1; cs += 32) {
        int ce = min(cs + 32, r1);
        float logreg;
        float cmax = -3.4e38f;
        // sweep A: logits
        for (int i = cs; i < ce; i++) {
            int s = csr_src[i];
            const float4* ps = (const float4*)(xl + (size_t)s * HID);
            float sum = 0.f;
            #pragma unroll
            for (int j = 0; j < 5; j++) {
                float4 x4 = ps[j * 32 + lane];
                float v;
                v = x4.x + xr4[j].x; v = v > 0.f ? v : NEGSLOPE * v; sum += v * at4[j].x;
                v = x4.y + xr4[j].y; v = v > 0.f ? v : NEGSLOPE * v; sum += v * at4[j].y;
                v = x4.z + xr4[j].z; v = v > 0.f ? v : NEGSLOPE * v; sum += v * at4[j].z;
                v = x4.w + xr4[j].w; v = v > 0.f ? v : NEGSLOPE * v; sum += v * at4[j].w;
            }
            #pragma unroll
            for (int o = 16; o > 0; o >>= 1)
                sum += __shfl_xor_sync(0xffffffffu, sum, o);
            if (lane == i - cs) logreg = sum;
            cmax = fmaxf(cmax, sum);
        }
        float nm = fmaxf(m, cmax);
        float sc = expf(m - nm);
        den *= sc;
        #pragma unroll
        for (int j = 0; j < 5; j++) {
            acc[j][0] *= sc; acc[j][1] *= sc; acc[j][2] *= sc; acc[j][3] *= sc;
        }
        m = nm;
        // sweep B: aggregate (rows L2-hot)
        for (int i = cs; i < ce; i++) {
            int s = csr_src[i];
            const float4* ps = (const float4*)(xl + (size_t)s * HID);
            float lg = __shfl_sync(0xffffffffu, logreg, i - cs);
            float ex = expf(lg - m);
            den += ex;
            #pragma unroll
            for (int j = 0; j < 5; j++) {
                float4 x4 = ps[j * 32 + lane];
                acc[j][0] += ex * x4.x;
                acc[j][1] += ex * x4.y;
                acc[j][2] += ex * x4.z;
                acc[j][3] += ex * x4.w;
            }
        }
    }
    float inv = 1.f / den;
    #pragma unroll
    for (int j = 0; j < 5; j++) {
        int cb = (j * 32 + lane) * 4;
        float o0 = acc[j][0] * inv + bias[cb];
        float o1 = acc[j][1] * inv + bias[cb + 1];
        float o2 = acc[j][2] * inv + bias[cb + 2];
        float o3 = acc[j][3] * inv + bias[cb + 3];
        __nv_bfloat16 h0 = __float2bfloat16(o0), h1 = __float2bfloat16(o1);
        __nv_bfloat16 h2 = __float2bfloat16(o2), h3 = __float2bfloat16(o3);
        __nv_bfloat162 hp0; hp0.x = h0; hp0.y = h1;
        __nv_bfloat162 hp1; hp1.x = h2; hp1.y = h3;
        __nv_bfloat162 lp0, lp1;
        lp0.x = __float2bfloat16(o0 - __bfloat162float(h0));
        lp0.y = __float2bfloat16(o1 - __bfloat162float(h1));
        lp1.x = __float2bfloat16(o2 - __bfloat162float(h2));
        lp1.y = __float2bfloat16(o3 - __bfloat162float(h3));
        *(__nv_bfloat162*)&ohi[(size_t)n * HID + cb]     = hp0;
        *(__nv_bfloat162*)&ohi[(size_t)n * HID + cb + 2] = hp1;
        *(__nv_bfloat162*)&olo[(size_t)n * HID + cb]     = lp0;
        *(__nv_bfloat162*)&olo[(size_t)n * HID + cb + 2] = lp1;
    }
}

// ---------------- GCN node aggregate + relu + fused pooling + cnt ----------
__global__ void k_gcn_node(const float* __restrict__ xw,
                           const int* __restrict__ rowptr,
                           const int* __restrict__ csr_src,
                           const float* __restrict__ dinv,
                           const float* __restrict__ bg,
                           const int* __restrict__ batch,
                           int* __restrict__ gmax, float* __restrict__ gsum,
                           float* __restrict__ cnt)
{
    int n = (blockIdx.x * blockDim.x + threadIdx.x) >> 5;
    int lane = threadIdx.x & 31;
    if (n >= NNODES) return;
    int r0 = rowptr[n], r1 = rowptr[n + 1];
    float dv = dinv[n];

    float acc[5][4];
    #pragma unroll
    for (int j = 0; j < 5; j++)
        #pragma unroll
        for (int q = 0; q < 4; q++) acc[j][q] = 0.f;

    for (int i = r0; i < r1; i++) {
        int s = csr_src[i];
        float nrm = dinv[s] * dv;
        const float4* ps = (const float4*)(xw + (size_t)s * HID);
        #pragma unroll
        for (int j = 0; j < 5; j++) {
            float4 v = ps[j * 32 + lane];
            acc[j][0] += nrm * v.x;
            acc[j][1] += nrm * v.y;
            acc[j][2] += nrm * v.z;
            acc[j][3] += nrm * v.w;
        }
    }
    int g = batch[n];
    if (lane == 0) atomicAdd(&cnt[g], 1.f);
    #pragma unroll
    for (int j = 0; j < 5; j++) {
        int cb = (j * 32 + lane) * 4;
        #pragma unroll
        for (int q = 0; q < 4; q++) {
            float o = fmaxf(acc[j][q] + bg[cb + q], 0.f);
            atomicMax(&gmax[g * HID + cb + q], __float_as_int(o));
            atomicAdd(&gsum[g * HID + cb + q], o);
        }
    }
}

// ---------------- pooling tail ---------------------------------------------
__global__ void k_final(const int* __restrict__ gmax, const float* __restrict__ gsum,
                        const float* __restrict__ cnt, float* __restrict__ out)
{
    int idx = blockIdx.x * blockDim.x + threadIdx.x;
    if (idx >= NGRAPH * HID) return;
    int g = idx / HID, c = idx % HID;
    out[(size_t)g * (2 * HID) + c]       = __int_as_float(gmax[idx]);
    out[(size_t)g * (2 * HID) + HID + c] = gsum[idx] / fmaxf(cnt[g], 1.f);
}

// ---------------- launch ---------------------------------------------------
extern "C" void kernel_launch(void* const* d_in, const int* in_sizes, int n_in,
                              void* d_out, int out_size)
{
    const float* x     = (const float*)d_in[0];
    const int*   ei    = (const int*)d_in[1];
    const int*   batch = (const int*)d_in[2];
    const float* Wl1 = (const float*)d_in[3];
    const float* Wr1 = (const float*)d_in[4];
    const float* a1  = (const float*)d_in[5];
    const float* b1  = (const float*)d_in[6];
    const float* Wl2 = (const float*)d_in[7];
    const float* Wr2 = (const float*)d_in[8];
    const float* a2  = (const float*)d_in[9];
    const float* b2  = (const float*)d_in[10];
    const float* Wg  = (const float*)d_in[11];
    const float* bg  = (const float*)d_in[12];
    float* out = (float*)d_out;

    float *A, *B, *dinv, *gsum, *cnt;
    int *rowptr, *cntbuf, *csr_src, *gmax;
    __nv_bfloat16 *xhi, *xlo, *hhi, *hlo;
    __nv_bfloat16 *w1lhi, *w1llo, *w1rhi, *w1rlo;
    __nv_bfloat16 *w2lhi, *w2llo, *w2rhi, *w2rlo, *wghi, *wglo;
    cudaGetSymbolAddress((void**)&A,       g_bufA);
    cudaGetSymbolAddress((void**)&B,       g_bufB);
    cudaGetSymbolAddress((void**)&dinv,    g_dinv);
    cudaGetSymbolAddress((void**)&rowptr,  g_rowptr);
    cudaGetSymbolAddress((void**)&cntbuf,  g_cntbuf);
    cudaGetSymbolAddress((void**)&csr_src, g_csr_src);
    cudaGetSymbolAddress((void**)&gmax,    g_gmax);
    cudaGetSymbolAddress((void**)&gsum,    g_gsum);
    cudaGetSymbolAddress((void**)&cnt,     g_cnt);
    cudaGetSymbolAddress((void**)&xhi,     g_xhi);
    cudaGetSymbolAddress((void**)&xlo,     g_xlo);
    cudaGetSymbolAddress((void**)&hhi,     g_hhi);
    cudaGetSymbolAddress((void**)&hlo,     g_hlo);
    cudaGetSymbolAddress((void**)&w1lhi,   g_w1lhi);
    cudaGetSymbolAddress((void**)&w1llo,   g_w1llo);
    cudaGetSymbolAddress((void**)&w1rhi,   g_w1rhi);
    cudaGetSymbolAddress((void**)&w1rlo,   g_w1rlo);
    cudaGetSymbolAddress((void**)&w2lhi,   g_w2lhi);
    cudaGetSymbolAddress((void**)&w2llo,   g_w2llo);
    cudaGetSymbolAddress((void**)&w2rhi,   g_w2rhi);
    cudaGetSymbolAddress((void**)&w2rlo,   g_w2rlo);
    cudaGetSymbolAddress((void**)&wghi,    g_wghi);
    cudaGetSymbolAddress((void**)&wglo,    g_wglo);

    static bool attr_set = false;
    if (!attr_set) {
        cudaFuncSetAttribute(k_hgemm, cudaFuncAttributeMaxDynamicSharedMemorySize, 2 * STG_ALL);
        attr_set = true;
    }

    const int T = 256;
    dim3 gg(HID / 128, (NNODES + 127) / 128);            // (5, 391)
    int nb   = (NNODES + T - 1) / T;
    int n2b  = (2 * NNODES + T - 1) / T;
    int epb  = (EPLUS + T - 1) / T;
    int ghb  = (NGRAPH * HID + T - 1) / T;
    int xsb  = (NNODES * KP1 + T - 1) / T;
    int w1b  = (HID * KP1 + T - 1) / T;
    int w2b  = (HID * HID + T - 1) / T;
    int nwN  = (NNODES * 32 + T - 1) / T;                // warp per node

    // ---- splits for layer 1, then the two layer-1 GEMMs ----
    // (launch #6 is a GEMM so ncu -s 5 -c 1 profiles it)
    k_split <<<xsb, T>>>(x, xhi, xlo, NNODES, INDIM, KP1);          // 1
    k_splitT<<<w1b, T>>>(Wl1, w1lhi, w1llo, INDIM, HID, KP1);       // 2
    k_splitT<<<w1b, T>>>(Wr1, w1rhi, w1rlo, INDIM, HID, KP1);       // 3
    k_splitT<<<w2b, T>>>(Wl2, w2lhi, w2llo, HID, HID, HID);         // 4
    k_hgemm<<<gg, T, 2 * STG_ALL>>>(xhi, xlo, w1lhi, w1llo, A, NNODES, HID, KP1);  // 5
    k_hgemm<<<gg, T, 2 * STG_ALL>>>(xhi, xlo, w1rhi, w1rlo, B, NNODES, HID, KP1);  // 6 <- profiled
    k_splitT<<<w2b, T>>>(Wr2, w2rhi, w2rlo, HID, HID, HID);
    k_splitT<<<w2b, T>>>(Wg,  wghi,  wglo,  HID, HID, HID);

    // ---- CSR build (dst-sorted, incl self loops) ----
    k_fill_i<<<n2b, T>>>(cntbuf, 0, 2 * NNODES);
    k_count<<<epb, T>>>(ei, cntbuf);
    k_scan<<<1, 1024>>>(cntbuf, rowptr);
    k_scatter<<<epb, T>>>(ei, rowptr, cntbuf + NNODES, csr_src);
    k_dinv<<<nb, T>>>(rowptr, dinv);

    // ---- Layer 1: fused GATv2 (heads=10, C=64) ----
    k_gat1_fused<<<nwN, T>>>(A, B, rowptr, csr_src, a1, b1, hhi, hlo);

    // ---- Layer 2: fused GATv2 (heads=1, C=640) ----
    k_hgemm<<<gg, T, 2 * STG_ALL>>>(hhi, hlo, w2lhi, w2llo, A, NNODES, HID, HID);
    k_hgemm<<<gg, T, 2 * STG_ALL>>>(hhi, hlo, w2rhi, w2rlo, B, NNODES, HID, HID);
    k_gat2_fused<<<nwN, T>>>(A, B, rowptr, csr_src, a2, b2, hhi, hlo);

    // ---- Layer 3: GCN + relu + fused pooling ----
    k_hgemm<<<gg, T, 2 * STG_ALL>>>(hhi, hlo, wghi, wglo, A, NNODES, HID, HID);
    k_pool_init<<<ghb, T>>>(gmax, gsum, cnt);
    k_gcn_node<<<nwN, T>>>(A, rowptr, csr_src, dinv, bg, batch, gmax, gsum, cnt);
    k_final<<<ghb, T>>>(gmax, gsum, cnt, out);
}

// round 16
// speedup vs baseline: 1.0158x; 1.0158x over previous
#include <cuda_runtime.h>
#include <cuda_bf16.h>
#include <cstdint>

#define NNODES 50000
#define NEDGES 150000
#define EPLUS  (NEDGES + NNODES)   // edges + self loops = 200000
#define NGRAPH 1024
#define INDIM  78
#define KP1    128                 // layer-1 K padded to 128
#define HID    640
#define XSTR   1280                // concatenated xl|xr row stride
#define HEADS  10
#define C1     64
#define NEGSLOPE 0.2f

// ---------------- scratch (static __device__ — no allocations allowed) -----
__device__ __align__(128) float g_bufAB[(size_t)NNODES * XSTR];  // xl|xr concat
__device__ float g_dinv[NNODES];
__device__ int   g_rowptr[NNODES + 1];
__device__ int   g_cntbuf[2 * NNODES];      // [0,N) count, [N,2N) scatter-fill
__device__ int   g_csr_src[EPLUS];
__device__ int   g_gmax[NGRAPH * HID];
__device__ float g_gsum[NGRAPH * HID];
__device__ float g_cnt [NGRAPH];
// bf16 split buffers
__device__ __align__(128) __nv_bfloat16 g_xhi[(size_t)NNODES * KP1];
__device__ __align__(128) __nv_bfloat16 g_xlo[(size_t)NNODES * KP1];
__device__ __align__(128) __nv_bfloat16 g_hhi[(size_t)NNODES * HID];
__device__ __align__(128) __nv_bfloat16 g_hlo[(size_t)NNODES * HID];
__device__ __align__(128) __nv_bfloat16 g_w1hi[2 * HID * KP1], g_w1lo[2 * HID * KP1];
__device__ __align__(128) __nv_bfloat16 g_w2hi[2 * HID * HID], g_w2lo[2 * HID * HID];
__device__ __align__(128) __nv_bfloat16 g_wghi[HID * HID],     g_wglo[HID * HID];

// ---------------- helpers --------------------------------------------------
__device__ __forceinline__ uint32_t smem_u32(const void* p) {
    return (uint32_t)__cvta_generic_to_shared(p);
}
#define LDSM4(r0, r1, r2, r3, addr) \
    asm volatile("ldmatrix.sync.aligned.m8n8.x4.shared.b16 {%0,%1,%2,%3}, [%4];" \
                 : "=r"(r0), "=r"(r1), "=r"(r2), "=r"(r3) : "r"(addr))
#define MMA16816(c, a0, a1, a2, a3, b0, b1) \
    asm volatile("mma.sync.aligned.m16n8k16.row.col.f32.bf16.bf16.f32 " \
                 "{%0,%1,%2,%3}, {%4,%5,%6,%7}, {%8,%9}, {%0,%1,%2,%3};" \
                 : "+f"((c)[0]), "+f"((c)[1]), "+f"((c)[2]), "+f"((c)[3]) \
                 : "r"(a0), "r"(a1), "r"(a2), "r"(a3), "r"(b0), "r"(b1))
__device__ __forceinline__ void cpasync16(uint32_t dst, const void* src, int sz) {
    asm volatile("cp.async.cg.shared.global [%0], [%1], 16, %2;"
                 :: "r"(dst), "l"(src), "r"(sz));
}
#define CP_COMMIT asm volatile("cp.async.commit_group;")
#define CP_WAIT1  asm volatile("cp.async.wait_group 1;")
#define CP_WAIT0  asm volatile("cp.async.wait_group 0;")

// ---------------- fills ----------------------------------------------------
__global__ void k_fill_i(int* p, int v, int n) {
    int i = blockIdx.x * blockDim.x + threadIdx.x;
    if (i < n) p[i] = v;
}
__global__ void k_pool_init(int* __restrict__ gmax, float* __restrict__ gsum,
                            float* __restrict__ cnt) {
    int i = blockIdx.x * blockDim.x + threadIdx.x;
    if (i < NGRAPH * HID) { gmax[i] = 0; gsum[i] = 0.f; }
    if (i < NGRAPH) cnt[i] = 0.f;
}

// ---------------- CSR build ------------------------------------------------
__global__ void k_count(const int* __restrict__ ei, int* __restrict__ cnt) {
    int e = blockIdx.x * blockDim.x + threadIdx.x;
    if (e >= EPLUS) return;
    int d = (e < NEDGES) ? ei[NEDGES + e] : e - NEDGES;
    atomicAdd(&cnt[d], 1);
}
__global__ void k_scan(const int* __restrict__ cnt, int* __restrict__ rowptr) {
    __shared__ int sh[1024];
    __shared__ int carry;
    if (threadIdx.x == 0) carry = 0;
    __syncthreads();
    for (int base = 0; base < NNODES; base += 1024) {
        int i = base + threadIdx.x;
        int v = (i < NNODES) ? cnt[i] : 0;
        sh[threadIdx.x] = v;
        __syncthreads();
        for (int off = 1; off < 1024; off <<= 1) {
            int t = (threadIdx.x >= off) ? sh[threadIdx.x - off] : 0;
            __syncthreads();
            sh[threadIdx.x] += t;
            __syncthreads();
        }
        if (i < NNODES) rowptr[i] = carry + sh[threadIdx.x] - v;
        __syncthreads();
        if (threadIdx.x == 1023) carry += sh[1023];
        __syncthreads();
    }
    if (threadIdx.x == 0) rowptr[NNODES] = EPLUS;
}
__global__ void k_scatter(const int* __restrict__ ei, const int* __restrict__ rowptr,
                          int* __restrict__ fill, int* __restrict__ csr_src) {
    int e = blockIdx.x * blockDim.x + threadIdx.x;
    if (e >= EPLUS) return;
    int s, d;
    if (e < NEDGES) { s = ei[e]; d = ei[NEDGES + e]; }
    else            { s = d = e - NEDGES; }
    int pos = rowptr[d] + atomicAdd(&fill[d], 1);
    csr_src[pos] = s;
}
__global__ void k_dinv(const int* __restrict__ rowptr, float* __restrict__ dinv) {
    int n = blockIdx.x * blockDim.x + threadIdx.x;
    if (n >= NNODES) return;
    dinv[n] = rsqrtf((float)(rowptr[n + 1] - rowptr[n]));   // >=1 (self loop)
}

// ---------------- bf16 hi/lo split prep ------------------------------------
__global__ void k_split(const float* __restrict__ src,
                        __nv_bfloat16* __restrict__ hi, __nv_bfloat16* __restrict__ lo,
                        int M, int K, int Kp)
{
    int idx = blockIdx.x * blockDim.x + threadIdx.x;
    if (idx >= M * Kp) return;
    int r = idx / Kp, k = idx - r * Kp;
    float v = (k < K) ? src[(size_t)r * K + k] : 0.f;
    __nv_bfloat16 h = __float2bfloat16(v);
    hi[idx] = h;
    lo[idx] = __float2bfloat16(v - __bfloat162float(h));
}
__global__ void k_splitT(const float* __restrict__ W,
                         __nv_bfloat16* __restrict__ hi, __nv_bfloat16* __restrict__ lo,
                         int K, int N, int Kp)
{
    int idx = blockIdx.x * blockDim.x + threadIdx.x;
    if (idx >= N * Kp) return;
    int n = idx / Kp, k = idx - n * Kp;
    float v = (k < K) ? W[(size_t)k * N + n] : 0.f;
    __nv_bfloat16 h = __float2bfloat16(v);
    hi[idx] = h;
    lo[idx] = __float2bfloat16(v - __bfloat162float(h));
}

// ---------------- split-bf16 HMMA GEMM, cp.async double buffer -------------
#define STG_T   10240               // bytes per tensor per stage (128*80)
#define STG_ALL 40960               // bytes per stage

__global__ __launch_bounds__(256, 2)
void k_hgemm(const __nv_bfloat16* __restrict__ Ahi, const __nv_bfloat16* __restrict__ Alo,
             const __nv_bfloat16* __restrict__ Bhi, const __nv_bfloat16* __restrict__ Blo,
             float* __restrict__ C, int M, int N, int K)
{
    extern __shared__ __align__(128) char smem[];
    const uint32_t sb = smem_u32(smem);
    const int tid = threadIdx.x, lane = tid & 31, wid = tid >> 5;
    const int wm = wid & 3, wn = wid >> 2;
    const int bm = blockIdx.y * 128, bn = blockIdx.x * 128;

    float c[2][8][4];
    #pragma unroll
    for (int i = 0; i < 2; i++)
        #pragma unroll
        for (int j = 0; j < 8; j++)
            #pragma unroll
            for (int q = 0; q < 4; q++) c[i][j][q] = 0.f;

    const int row = tid >> 1, half = tid & 1;
    const bool va = (bm + row) < M;
    const int szA = va ? 16 : 0;
    const char* gAh = (const char*)(Ahi + (size_t)(bm + row) * K) + half * 32;
    const char* gAl = (const char*)(Alo + (size_t)(bm + row) * K) + half * 32;
    const char* gBh = (const char*)(Bhi + (size_t)(bn + row) * K) + half * 32;
    const char* gBl = (const char*)(Blo + (size_t)(bn + row) * K) + half * 32;
    const uint32_t dOff = (uint32_t)(row * 80 + half * 32);

#define LOAD_STAGE(s, k0) do {                                              \
        uint32_t b_ = sb + (uint32_t)((s) & 1) * STG_ALL;                   \
        size_t kb_ = (size_t)(k0) * 2;                                      \
        cpasync16(b_ + 0 * STG_T + dOff,      gAh + kb_,      szA);         \
        cpasync16(b_ + 0 * STG_T + dOff + 16, gAh + kb_ + 16, szA);         \
        cpasync16(b_ + 1 * STG_T + dOff,      gAl + kb_,      szA);         \
        cpasync16(b_ + 1 * STG_T + dOff + 16, gAl + kb_ + 16, szA);         \
        cpasync16(b_ + 2 * STG_T + dOff,      gBh + kb_,      16);          \
        cpasync16(b_ + 2 * STG_T + dOff + 16, gBh + kb_ + 16, 16);          \
        cpasync16(b_ + 3 * STG_T + dOff,      gBl + kb_,      16);          \
        cpasync16(b_ + 3 * STG_T + dOff + 16, gBl + kb_ + 16, 16);          \
    } while (0)

    const uint32_t a_mr = (lane & 7) + ((lane >> 3) & 1) * 8;
    const uint32_t a_kc = (lane >> 4) * 8;
    const uint32_t b_nr = ((lane >> 4) & 1) * 8 + (lane & 7);
    const uint32_t b_kc = ((lane >> 3) & 1) * 8;

    const int nst = K >> 5;
    LOAD_STAGE(0, 0);
    CP_COMMIT;
    for (int s = 0; s < nst; s++) {
        if (s + 1 < nst) { LOAD_STAGE(s + 1, (s + 1) << 5); CP_COMMIT; CP_WAIT1; }
        else             { CP_WAIT0; }
        __syncthreads();

        uint32_t base = sb + (uint32_t)(s & 1) * STG_ALL;
        #pragma unroll
        for (int ksub = 0; ksub < 2; ksub++) {
            uint32_t ko = ksub * 32;
            uint32_t ah[2][4], al[2][4];
            #pragma unroll
            for (int mt = 0; mt < 2; mt++) {
                uint32_t aaddr = (uint32_t)((wm * 32 + mt * 16 + a_mr) * 80) + ko + a_kc * 2;
                LDSM4(ah[mt][0], ah[mt][1], ah[mt][2], ah[mt][3], base + 0 * STG_T + aaddr);
                LDSM4(al[mt][0], al[mt][1], al[mt][2], al[mt][3], base + 1 * STG_T + aaddr);
            }
            #pragma unroll
            for (int bg = 0; bg < 4; bg++) {
                uint32_t baddr = (uint32_t)((wn * 64 + bg * 16 + b_nr) * 80) + ko + b_kc * 2;
                uint32_t bh0, bh1, bh2, bh3, bl0, bl1, bl2, bl3;
                LDSM4(bh0, bh1, bh2, bh3, base + 2 * STG_T + baddr);
                LDSM4(bl0, bl1, bl2, bl3, base + 3 * STG_T + baddr);
                #pragma unroll
                for (int mt = 0; mt < 2; mt++) {
                    float* c0 = c[mt][bg * 2];
                    float* c1 = c[mt][bg * 2 + 1];
                    MMA16816(c0, ah[mt][0], ah[mt][1], ah[mt][2], ah[mt][3], bh0, bh1);
                    MMA16816(c0, ah[mt][0], ah[mt][1], ah[mt][2], ah[mt][3], bl0, bl1);
                    MMA16816(c0, al[mt][0], al[mt][1], al[mt][2], al[mt][3], bh0, bh1);
                    MMA16816(c1, ah[mt][0], ah[mt][1], ah[mt][2], ah[mt][3], bh2, bh3);
                    MMA16816(c1, ah[mt][0], ah[mt][1], ah[mt][2], ah[mt][3], bl2, bl3);
                    MMA16816(c1, al[mt][0], al[mt][1], al[mt][2], al[mt][3], bh2, bh3);
                }
            }
        }
        __syncthreads();
    }
#undef LOAD_STAGE

    const int rbase = bm + wm * 32 + (lane >> 2);
    const int cbase = bn + wn * 64 + (lane & 3) * 2;
    #pragma unroll
    for (int mt = 0; mt < 2; mt++) {
        #pragma unroll
        for (int nt = 0; nt < 8; nt++) {
            int rr = rbase + mt * 16;
            int cc = cbase + nt * 8;
            if (rr < M)
                *(float2*)&C[(size_t)rr * N + cc] = make_float2(c[mt][nt][0], c[mt][nt][1]);
            if (rr + 8 < M)
                *(float2*)&C[(size_t)(rr + 8) * N + cc] = make_float2(c[mt][nt][2], c[mt][nt][3]);
        }
    }
}

// ---------------- fused GATv2 layer 1 (H=10, C=64), warp per node ----------
// ab rows: [xl(640) | xr(640)], stride XSTR.
__global__ void k_gat1_fused(const float* __restrict__ ab,
                             const int* __restrict__ rowptr,
                             const int* __restrict__ csr_src,
                             const float* __restrict__ att,
                             const float* __restrict__ bias,
                             __nv_bfloat16* __restrict__ ohi,
                             __nv_bfloat16* __restrict__ olo)
{
    int n = (blockIdx.x * blockDim.x + threadIdx.x) >> 5;
    int lane = threadIdx.x & 31;
    if (n >= NNODES) return;
    int r0 = rowptr[n], r1 = rowptr[n + 1];
    int k16 = lane & 15;

    float4 xr4[5], at4[5];
    const float4* pr = (const float4*)(ab + (size_t)n * XSTR + HID);
    const float4* pa = (const float4*)att;
    #pragma unroll
    for (int j = 0; j < 5; j++) {
        xr4[j] = pr[j * 32 + lane];
        at4[j] = pa[j * 32 + lane];
    }

    float m[5], den[5], acc[5][4];
    #pragma unroll
    for (int j = 0; j < 5; j++) {
        m[j] = -3.4e38f; den[j] = 0.f;
        acc[j][0] = acc[j][1] = acc[j][2] = acc[j][3] = 0.f;
    }

    for (int cs = r0; cs < r1; cs += 16) {
        int ce = min(cs + 16, r1);
        float logreg[5];
        float cmax[5];
        #pragma unroll
        for (int j = 0; j < 5; j++) cmax[j] = -3.4e38f;

        for (int i = cs; i < ce; i++) {
            int s = csr_src[i];
            const float4* ps = (const float4*)(ab + (size_t)s * XSTR);
            float part[5];
            #pragma unroll
            for (int j = 0; j < 5; j++) {
                float4 x4 = ps[j * 32 + lane];
                float v, sum = 0.f;
                v = x4.x + xr4[j].x; v = v > 0.f ? v : NEGSLOPE * v; sum += v * at4[j].x;
                v = x4.y + xr4[j].y; v = v > 0.f ? v : NEGSLOPE * v; sum += v * at4[j].y;
                v = x4.z + xr4[j].z; v = v > 0.f ? v : NEGSLOPE * v; sum += v * at4[j].z;
                v = x4.w + xr4[j].w; v = v > 0.f ? v : NEGSLOPE * v; sum += v * at4[j].w;
                part[j] = sum;
            }
            #pragma unroll
            for (int o = 8; o > 0; o >>= 1) {
                #pragma unroll
                for (int j = 0; j < 5; j++)
                    part[j] += __shfl_xor_sync(0xffffffffu, part[j], o);
            }
            int k = i - cs;
            #pragma unroll
            for (int j = 0; j < 5; j++) {
                if (k16 == k) logreg[j] = part[j];
                cmax[j] = fmaxf(cmax[j], part[j]);
            }
        }
        #pragma unroll
        for (int j = 0; j < 5; j++) {
            float nm = fmaxf(m[j], cmax[j]);
            float sc = expf(m[j] - nm);
            den[j] *= sc;
            acc[j][0] *= sc; acc[j][1] *= sc; acc[j][2] *= sc; acc[j][3] *= sc;
            m[j] = nm;
        }
        for (int i = cs; i < ce; i++) {
            int s = csr_src[i];
            const float4* ps = (const float4*)(ab + (size_t)s * XSTR);
            int srcl = (lane & 16) | (i - cs);
            #pragma unroll
            for (int j = 0; j < 5; j++) {
                float lg = __shfl_sync(0xffffffffu, logreg[j], srcl);
                float ex = expf(lg - m[j]);
                den[j] += ex;
                float4 x4 = ps[j * 32 + lane];
                acc[j][0] += ex * x4.x;
                acc[j][1] += ex * x4.y;
                acc[j][2] += ex * x4.z;
                acc[j][3] += ex * x4.w;
            }
        }
    }
    #pragma unroll
    for (int j = 0; j < 5; j++) {
        float inv = 1.f / den[j];
        int cb = (j * 32 + lane) * 4;
        float o0 = acc[j][0] * inv + bias[cb];
        float o1 = acc[j][1] * inv + bias[cb + 1];
        float o2 = acc[j][2] * inv + bias[cb + 2];
        float o3 = acc[j][3] * inv + bias[cb + 3];
        o0 = o0 > 0.f ? o0 : expm1f(o0);
        o1 = o1 > 0.f ? o1 : expm1f(o1);
        o2 = o2 > 0.f ? o2 : expm1f(o2);
        o3 = o3 > 0.f ? o3 : expm1f(o3);
        __nv_bfloat16 h0 = __float2bfloat16(o0), h1 = __float2bfloat16(o1);
        __nv_bfloat16 h2 = __float2bfloat16(o2), h3 = __float2bfloat16(o3);
        __nv_bfloat162 hp0; hp0.x = h0; hp0.y = h1;
        __nv_bfloat162 hp1; hp1.x = h2; hp1.y = h3;
        __nv_bfloat162 lp0, lp1;
        lp0.x = __float2bfloat16(o0 - __bfloat162float(h0));
        lp0.y = __float2bfloat16(o1 - __bfloat162float(h1));
        lp1.x = __float2bfloat16(o2 - __bfloat162float(h2));
        lp1.y = __float2bfloat16(o3 - __bfloat162float(h3));
        *(__nv_bfloat162*)&ohi[(size_t)n * HID + cb]     = hp0;
        *(__nv_bfloat162*)&ohi[(size_t)n * HID + cb + 2] = hp1;
        *(__nv_bfloat162*)&olo[(size_t)n * HID + cb]     = lp0;
        *(__nv_bfloat162*)&olo[(size_t)n * HID + cb + 2] = lp1;
    }
}

// ---------------- fused GATv2 layer 2 (H=1, C=640), warp per node ----------
__global__ void k_gat2_fused(const float* __restrict__ ab,
                             const int* __restrict__ rowptr,
                             const int* __restrict__ csr_src,
                             const float* __restrict__ att,
                             const float* __restrict__ bias,
                             __nv_bfloat16* __restrict__ ohi,
                             __nv_bfloat16* __restrict__ olo)
{
    int n = (blockIdx.x * blockDim.x + threadIdx.x) >> 5;
    int lane = threadIdx.x & 31;
    if (n >= NNODES) return;
    int r0 = rowptr[n], r1 = rowptr[n + 1];

    float4 xr4[5], at4[5];
    const float4* pr = (const float4*)(ab + (size_t)n * XSTR + HID);
    const float4* pa = (const float4*)att;
    #pragma unroll
    for (int j = 0; j < 5; j++) {
        xr4[j] = pr[j * 32 + lane];
        at4[j] = pa[j * 32 + lane];
    }

    float m = -3.4e38f, den = 0.f;
    float acc[5][4];
    #pragma unroll
    for (int j = 0; j < 5; j++)
        #pragma unroll
        for (int q = 0; q < 4; q++) acc[j][q] = 0.f;

    for (int cs = r0; cs < r1; cs += 32) {
        int ce = min(cs + 32, r1);
        float logreg;
        float cmax = -3.4e38f;
        for (int i = cs; i < ce; i++) {
            int s = csr_src[i];
            const float4* ps = (const float4*)(ab + (size_t)s * XSTR);
            float sum = 0.f;
            #pragma unroll
            for (int j = 0; j < 5; j++) {
                float4 x4 = ps[j * 32 + lane];
                float v;
                v = x4.x + xr4[j].x; v = v > 0.f ? v : NEGSLOPE * v; sum += v * at4[j].x;
                v = x4.y + xr4[j].y; v = v > 0.f ? v : NEGSLOPE * v; sum += v * at4[j].y;
                v = x4.z + xr4[j].z; v = v > 0.f ? v : NEGSLOPE * v; sum += v * at4[j].z;
                v = x4.w + xr4[j].w; v = v > 0.f ? v : NEGSLOPE * v; sum += v * at4[j].w;
            }
            #pragma unroll
            for (int o = 16; o > 0; o >>= 1)
                sum += __shfl_xor_sync(0xffffffffu, sum, o);
            if (lane == i - cs) logreg = sum;
            cmax = fmaxf(cmax, sum);
        }
        float nm = fmaxf(m, cmax);
        float sc = expf(m - nm);
        den *= sc;
        #pragma unroll
        for (int j = 0; j < 5; j++) {
            acc[j][0] *= sc; acc[j][1] *= sc; acc[j][2] *= sc; acc[j][3] *= sc;
        }
        m = nm;
        for (int i = cs; i < ce; i++) {
            int s = csr_src[i];
            const float4* ps = (const float4*)(ab + (size_t)s * XSTR);
            float lg = __shfl_sync(0xffffffffu, logreg, i - cs);
            float ex = expf(lg - m);
            den += ex;
            #pragma unroll
            for (int j = 0; j < 5; j++) {
                float4 x4 = ps[j * 32 + lane];
                acc[j][0] += ex * x4.x;
                acc[j][1] += ex * x4.y;
                acc[j][2] += ex * x4.z;
                acc[j][3] += ex * x4.w;
            }
        }
    }
    float inv = 1.f / den;
    #pragma unroll
    for (int j = 0; j < 5; j++) {
        int cb = (j * 32 + lane) * 4;
        float o0 = acc[j][0] * inv + bias[cb];
        float o1 = acc[j][1] * inv + bias[cb + 1];
        float o2 = acc[j][2] * inv + bias[cb + 2];
        float o3 = acc[j][3] * inv + bias[cb + 3];
        __nv_bfloat16 h0 = __float2bfloat16(o0), h1 = __float2bfloat16(o1);
        __nv_bfloat16 h2 = __float2bfloat16(o2), h3 = __float2bfloat16(o3);
        __nv_bfloat162 hp0; hp0.x = h0; hp0.y = h1;
        __nv_bfloat162 hp1; hp1.x = h2; hp1.y = h3;
        __nv_bfloat162 lp0, lp1;
        lp0.x = __float2bfloat16(o0 - __bfloat162float(h0));
        lp0.y = __float2bfloat16(o1 - __bfloat162float(h1));
        lp1.x = __float2bfloat16(o2 - __bfloat162float(h2));
        lp1.y = __float2bfloat16(o3 - __bfloat162float(h3));
        *(__nv_bfloat162*)&ohi[(size_t)n * HID + cb]     = hp0;
        *(__nv_bfloat162*)&ohi[(size_t)n * HID + cb + 2] = hp1;
        *(__nv_bfloat162*)&olo[(size_t)n * HID + cb]     = lp0;
        *(__nv_bfloat162*)&olo[(size_t)n * HID + cb + 2] = lp1;
    }
}

// ---------------- GCN node aggregate + relu + fused pooling + cnt ----------
__global__ void k_gcn_node(const float* __restrict__ xw,
                           const int* __restrict__ rowptr,
                           const int* __restrict__ csr_src,
                           const float* __restrict__ dinv,
                           const float* __restrict__ bg,
                           const int* __restrict__ batch,
                           int* __restrict__ gmax, float* __restrict__ gsum,
                           float* __restrict__ cnt)
{
    int n = (blockIdx.x * blockDim.x + threadIdx.x) >> 5;
    int lane = threadIdx.x & 31;
    if (n >= NNODES) return;
    int r0 = rowptr[n], r1 = rowptr[n + 1];
    float dv = dinv[n];

    float acc[5][4];
    #pragma unroll
    for (int j = 0; j < 5; j++)
        #pragma unroll
        for (int q = 0; q < 4; q++) acc[j][q] = 0.f;

    for (int i = r0; i < r1; i++) {
        int s = csr_src[i];
        float nrm = dinv[s] * dv;
        const float4* ps = (const float4*)(xw + (size_t)s * HID);
        #pragma unroll
        for (int j = 0; j < 5; j++) {
            float4 v = ps[j * 32 + lane];
            acc[j][0] += nrm * v.x;
            acc[j][1] += nrm * v.y;
            acc[j][2] += nrm * v.z;
            acc[j][3] += nrm * v.w;
        }
    }
    int g = batch[n];
    if (lane == 0) atomicAdd(&cnt[g], 1.f);
    #pragma unroll
    for (int j = 0; j < 5; j++) {
        int cb = (j * 32 + lane) * 4;
        #pragma unroll
        for (int q = 0; q < 4; q++) {
            float o = fmaxf(acc[j][q] + bg[cb + q], 0.f);
            atomicMax(&gmax[g * HID + cb + q], __float_as_int(o));
            atomicAdd(&gsum[g * HID + cb + q], o);
        }
    }
}

// ---------------- pooling tail ---------------------------------------------
__global__ void k_final(const int* __restrict__ gmax, const float* __restrict__ gsum,
                        const float* __restrict__ cnt, float* __restrict__ out)
{
    int idx = blockIdx.x * blockDim.x + threadIdx.x;
    if (idx >= NGRAPH * HID) return;
    int g = idx / HID, c = idx % HID;
    out[(size_t)g * (2 * HID) + c]       = __int_as_float(gmax[idx]);
    out[(size_t)g * (2 * HID) + HID + c] = gsum[idx] / fmaxf(cnt[g], 1.f);
}

// ---------------- launch ---------------------------------------------------
extern "C" void kernel_launch(void* const* d_in, const int* in_sizes, int n_in,
                              void* d_out, int out_size)
{
    const float* x     = (const float*)d_in[0];
    const int*   ei    = (const int*)d_in[1];
    const int*   batch = (const int*)d_in[2];
    const float* Wl1 = (const float*)d_in[3];
    const float* Wr1 = (const float*)d_in[4];
    const float* a1  = (const float*)d_in[5];
    const float* b1  = (const float*)d_in[6];
    const float* Wl2 = (const float*)d_in[7];
    const float* Wr2 = (const float*)d_in[8];
    const float* a2  = (const float*)d_in[9];
    const float* b2  = (const float*)d_in[10];
    const float* Wg  = (const float*)d_in[11];
    const float* bg  = (const float*)d_in[12];
    float* out = (float*)d_out;

    float *AB, *dinv, *gsum, *cnt;
    int *rowptr, *cntbuf, *csr_src, *gmax;
    __nv_bfloat16 *xhi, *xlo, *hhi, *hlo;
    __nv_bfloat16 *w1hi, *w1lo, *w2hi, *w2lo, *wghi, *wglo;
    cudaGetSymbolAddress((void**)&AB,      g_bufAB);
    cudaGetSymbolAddress((void**)&dinv,    g_dinv);
    cudaGetSymbolAddress((void**)&rowptr,  g_rowptr);
    cudaGetSymbolAddress((void**)&cntbuf,  g_cntbuf);
    cudaGetSymbolAddress((void**)&csr_src, g_csr_src);
    cudaGetSymbolAddress((void**)&gmax,    g_gmax);
    cudaGetSymbolAddress((void**)&gsum,    g_gsum);
    cudaGetSymbolAddress((void**)&cnt,     g_cnt);
    cudaGetSymbolAddress((void**)&xhi,     g_xhi);
    cudaGetSymbolAddress((void**)&xlo,     g_xlo);
    cudaGetSymbolAddress((void**)&hhi,     g_hhi);
    cudaGetSymbolAddress((void**)&hlo,     g_hlo);
    cudaGetSymbolAddress((void**)&w1hi,    g_w1hi);
    cudaGetSymbolAddress((void**)&w1lo,    g_w1lo);
    cudaGetSymbolAddress((void**)&w2hi,    g_w2hi);
    cudaGetSymbolAddress((void**)&w2lo,    g_w2lo);
    cudaGetSymbolAddress((void**)&wghi,    g_wghi);
    cudaGetSymbolAddress((void**)&wglo,    g_wglo);

    // one-time infra (created on the uncaptured correctness call)
    static cudaStream_t s2 = nullptr;
    static cudaEvent_t evFork = nullptr, evJoin = nullptr;
    static bool attr_set = false;
    if (!attr_set) {
        cudaFuncSetAttribute(k_hgemm, cudaFuncAttributeMaxDynamicSharedMemorySize, 2 * STG_ALL);
        cudaStreamCreateWithFlags(&s2, cudaStreamNonBlocking);
        cudaEventCreateWithFlags(&evFork, cudaEventDisableTiming);
        cudaEventCreateWithFlags(&evJoin, cudaEventDisableTiming);
        attr_set = true;
    }

    const int T = 256;
    dim3 gg2(2 * HID / 128, (NNODES + 127) / 128);       // (10, 391) concat
    dim3 gg1(HID / 128, (NNODES + 127) / 128);           // (5, 391)
    int nb   = (NNODES + T - 1) / T;
    int n2b  = (2 * NNODES + T - 1) / T;
    int epb  = (EPLUS + T - 1) / T;
    int ghb  = (NGRAPH * HID + T - 1) / T;
    int xsb  = (NNODES * KP1 + T - 1) / T;
    int w1b  = (HID * KP1 + T - 1) / T;
    int w2b  = (HID * HID + T - 1) / T;
    int nwN  = (NNODES * 32 + T - 1) / T;                // warp per node

    // ---- main stream: layer-1 prep ----
    k_split <<<xsb, T>>>(x, xhi, xlo, NNODES, INDIM, KP1);
    k_splitT<<<w1b, T>>>(Wl1, w1hi, w1lo, INDIM, HID, KP1);
    k_splitT<<<w1b, T>>>(Wr1, w1hi + (size_t)HID * KP1, w1lo + (size_t)HID * KP1,
                         INDIM, HID, KP1);

    // ---- fork: CSR build + layer-2/3 weight splits + pool init on s2 ----
    cudaEventRecord(evFork, 0);
    cudaStreamWaitEvent(s2, evFork, 0);
    k_fill_i <<<n2b, T, 0, s2>>>(cntbuf, 0, 2 * NNODES);
    k_count  <<<epb, T, 0, s2>>>(ei, cntbuf);
    k_scan   <<<1, 1024, 0, s2>>>(cntbuf, rowptr);
    k_scatter<<<epb, T, 0, s2>>>(ei, rowptr, cntbuf + NNODES, csr_src);
    k_dinv   <<<nb, T, 0, s2>>>(rowptr, dinv);
    k_splitT <<<w2b, T, 0, s2>>>(Wl2, w2hi, w2lo, HID, HID, HID);
    k_splitT <<<w2b, T, 0, s2>>>(Wr2, w2hi + (size_t)HID * HID, w2lo + (size_t)HID * HID,
                                 HID, HID, HID);
    k_splitT <<<w2b, T, 0, s2>>>(Wg, wghi, wglo, HID, HID, HID);
    k_pool_init<<<ghb, T, 0, s2>>>(gmax, gsum, cnt);
    cudaEventRecord(evJoin, s2);

    // ---- Layer 1: concat GEMM (xl|xr), then fused GATv2 ----
    k_hgemm<<<gg2, T, 2 * STG_ALL>>>(xhi, xlo, w1hi, w1lo, AB, NNODES, XSTR, KP1);
    cudaStreamWaitEvent(0, evJoin, 0);
    k_gat1_fused<<<nwN, T>>>(AB, rowptr, csr_src, a1, b1, hhi, hlo);

    // ---- Layer 2: concat GEMM, fused GATv2 ----
    k_hgemm<<<gg2, T, 2 * STG_ALL>>>(hhi, hlo, w2hi, w2lo, AB, NNODES, XSTR, HID);
    k_gat2_fused<<<nwN, T>>>(AB, rowptr, csr_src, a2, b2, hhi, hlo);

    // ---- Layer 3: GCN + relu + fused pooling ----
    k_hgemm<<<gg1, T, 2 * STG_ALL>>>(hhi, hlo, wghi, wglo, AB, NNODES, HID, HID);
    k_gcn_node<<<nwN, T>>>(AB, rowptr, csr_src, dinv, bg, batch, gmax, gsum, cnt);
    k_final<<<ghb, T>>>(gmax, gsum, cnt, out);
}

// round 17
// speedup vs baseline: 1.0224x; 1.0065x over previous
#include <cuda_runtime.h>
#include <cuda_bf16.h>
#include <cstdint>

#define NNODES 50000
#define NEDGES 150000
#define EPLUS  (NEDGES + NNODES)   // edges + self loops = 200000
#define NGRAPH 1024
#define INDIM  78
#define KP1    128                 // layer-1 K padded to 128
#define HID    640
#define XSTR   1280                // concatenated xl|xr row stride
#define HEADS  10
#define C1     64
#define NEGSLOPE 0.2f

// ---------------- scratch (static __device__ — no allocations allowed) -----
__device__ __align__(128) float g_bufAB[(size_t)NNODES * XSTR];  // xl|xr concat
__device__ float g_dinv[NNODES];
__device__ int   g_rowptr[NNODES + 1];
__device__ int   g_cntbuf[2 * NNODES];      // [0,N) count, [N,2N) scatter-fill
__device__ int   g_csr_src[EPLUS];
__device__ int   g_gmax[NGRAPH * HID];
__device__ float g_gsum[NGRAPH * HID];
__device__ float g_cnt [NGRAPH];
// bf16 split buffers
__device__ __align__(128) __nv_bfloat16 g_xhi[(size_t)NNODES * KP1];
__device__ __align__(128) __nv_bfloat16 g_xlo[(size_t)NNODES * KP1];
__device__ __align__(128) __nv_bfloat16 g_hhi[(size_t)NNODES * HID];
__device__ __align__(128) __nv_bfloat16 g_hlo[(size_t)NNODES * HID];
__device__ __align__(128) __nv_bfloat16 g_w1hi[2 * HID * KP1], g_w1lo[2 * HID * KP1];
__device__ __align__(128) __nv_bfloat16 g_w2hi[2 * HID * HID], g_w2lo[2 * HID * HID];
__device__ __align__(128) __nv_bfloat16 g_wghi[HID * HID],     g_wglo[HID * HID];

// ---------------- helpers --------------------------------------------------
__device__ __forceinline__ uint32_t smem_u32(const void* p) {
    return (uint32_t)__cvta_generic_to_shared(p);
}
#define LDSM4(r0, r1, r2, r3, addr) \
    asm volatile("ldmatrix.sync.aligned.m8n8.x4.shared.b16 {%0,%1,%2,%3}, [%4];" \
                 : "=r"(r0), "=r"(r1), "=r"(r2), "=r"(r3) : "r"(addr))
#define MMA16816(c, a0, a1, a2, a3, b0, b1) \
    asm volatile("mma.sync.aligned.m16n8k16.row.col.f32.bf16.bf16.f32 " \
                 "{%0,%1,%2,%3}, {%4,%5,%6,%7}, {%8,%9}, {%0,%1,%2,%3};" \
                 : "+f"((c)[0]), "+f"((c)[1]), "+f"((c)[2]), "+f"((c)[3]) \
                 : "r"(a0), "r"(a1), "r"(a2), "r"(a3), "r"(b0), "r"(b1))
__device__ __forceinline__ void cpasync16(uint32_t dst, const void* src, int sz) {
    asm volatile("cp.async.cg.shared.global [%0], [%1], 16, %2;"
                 :: "r"(dst), "l"(src), "r"(sz));
}
#define CP_COMMIT asm volatile("cp.async.commit_group;")
#define CP_WAIT1  asm volatile("cp.async.wait_group 1;")
#define CP_WAIT0  asm volatile("cp.async.wait_group 0;")

// ---------------- fills ----------------------------------------------------
__global__ void k_fill_i(int* p, int v, int n) {
    int i = blockIdx.x * blockDim.x + threadIdx.x;
    if (i < n) p[i] = v;
}
__global__ void k_pool_init(int* __restrict__ gmax, float* __restrict__ gsum,
                            float* __restrict__ cnt) {
    int i = blockIdx.x * blockDim.x + threadIdx.x;
    if (i < NGRAPH * HID) { gmax[i] = 0; gsum[i] = 0.f; }
    if (i < NGRAPH) cnt[i] = 0.f;
}

// ---------------- CSR build ------------------------------------------------
__global__ void k_count(const int* __restrict__ ei, int* __restrict__ cnt) {
    int e = blockIdx.x * blockDim.x + threadIdx.x;
    if (e >= EPLUS) return;
    int d = (e < NEDGES) ? ei[NEDGES + e] : e - NEDGES;
    atomicAdd(&cnt[d], 1);
}
__global__ void k_scan(const int* __restrict__ cnt, int* __restrict__ rowptr) {
    __shared__ int sh[1024];
    __shared__ int carry;
    if (threadIdx.x == 0) carry = 0;
    __syncthreads();
    for (int base = 0; base < NNODES; base += 1024) {
        int i = base + threadIdx.x;
        int v = (i < NNODES) ? cnt[i] : 0;
        sh[threadIdx.x] = v;
        __syncthreads();
        for (int off = 1; off < 1024; off <<= 1) {
            int t = (threadIdx.x >= off) ? sh[threadIdx.x - off] : 0;
            __syncthreads();
            sh[threadIdx.x] += t;
            __syncthreads();
        }
        if (i < NNODES) rowptr[i] = carry + sh[threadIdx.x] - v;
        __syncthreads();
        if (threadIdx.x == 1023) carry += sh[1023];
        __syncthreads();
    }
    if (threadIdx.x == 0) rowptr[NNODES] = EPLUS;
}
__global__ void k_scatter(const int* __restrict__ ei, const int* __restrict__ rowptr,
                          int* __restrict__ fill, int* __restrict__ csr_src) {
    int e = blockIdx.x * blockDim.x + threadIdx.x;
    if (e >= EPLUS) return;
    int s, d;
    if (e < NEDGES) { s = ei[e]; d = ei[NEDGES + e]; }
    else            { s = d = e - NEDGES; }
    int pos = rowptr[d] + atomicAdd(&fill[d], 1);
    csr_src[pos] = s;
}
__global__ void k_dinv(const int* __restrict__ rowptr, float* __restrict__ dinv) {
    int n = blockIdx.x * blockDim.x + threadIdx.x;
    if (n >= NNODES) return;
    dinv[n] = rsqrtf((float)(rowptr[n + 1] - rowptr[n]));   // >=1 (self loop)
}

// ---------------- bf16 hi/lo split prep ------------------------------------
__global__ void k_split(const float* __restrict__ src,
                        __nv_bfloat16* __restrict__ hi, __nv_bfloat16* __restrict__ lo,
                        int M, int K, int Kp)
{
    int idx = blockIdx.x * blockDim.x + threadIdx.x;
    if (idx >= M * Kp) return;
    int r = idx / Kp, k = idx - r * Kp;
    float v = (k < K) ? src[(size_t)r * K + k] : 0.f;
    __nv_bfloat16 h = __float2bfloat16(v);
    hi[idx] = h;
    lo[idx] = __float2bfloat16(v - __bfloat162float(h));
}
__global__ void k_splitT(const float* __restrict__ W,
                         __nv_bfloat16* __restrict__ hi, __nv_bfloat16* __restrict__ lo,
                         int K, int N, int Kp)
{
    int idx = blockIdx.x * blockDim.x + threadIdx.x;
    if (idx >= N * Kp) return;
    int n = idx / Kp, k = idx - n * Kp;
    float v = (k < K) ? W[(size_t)k * N + n] : 0.f;
    __nv_bfloat16 h = __float2bfloat16(v);
    hi[idx] = h;
    lo[idx] = __float2bfloat16(v - __bfloat162float(h));
}

// ---------------- split-bf16 HMMA GEMM, cp.async double buffer -------------
#define STG_T   10240               // bytes per tensor per stage (128*80)
#define STG_ALL 40960               // bytes per stage

__global__ __launch_bounds__(256, 2)
void k_hgemm(const __nv_bfloat16* __restrict__ Ahi, const __nv_bfloat16* __restrict__ Alo,
             const __nv_bfloat16* __restrict__ Bhi, const __nv_bfloat16* __restrict__ Blo,
             float* __restrict__ C, int M, int N, int K)
{
    extern __shared__ __align__(128) char smem[];
    const uint32_t sb = smem_u32(smem);
    const int tid = threadIdx.x, lane = tid & 31, wid = tid >> 5;
    const int wm = wid & 3, wn = wid >> 2;
    const int bm = blockIdx.y * 128, bn = blockIdx.x * 128;

    float c[2][8][4];
    #pragma unroll
    for (int i = 0; i < 2; i++)
        #pragma unroll
        for (int j = 0; j < 8; j++)
            #pragma unroll
            for (int q = 0; q < 4; q++) c[i][j][q] = 0.f;

    const int row = tid >> 1, half = tid & 1;
    const bool va = (bm + row) < M;
    const int szA = va ? 16 : 0;
    const char* gAh = (const char*)(Ahi + (size_t)(bm + row) * K) + half * 32;
    const char* gAl = (const char*)(Alo + (size_t)(bm + row) * K) + half * 32;
    const char* gBh = (const char*)(Bhi + (size_t)(bn + row) * K) + half * 32;
    const char* gBl = (const char*)(Blo + (size_t)(bn + row) * K) + half * 32;
    const uint32_t dOff = (uint32_t)(row * 80 + half * 32);

#define LOAD_STAGE(s, k0) do {                                              \
        uint32_t b_ = sb + (uint32_t)((s) & 1) * STG_ALL;                   \
        size_t kb_ = (size_t)(k0) * 2;                                      \
        cpasync16(b_ + 0 * STG_T + dOff,      gAh + kb_,      szA);         \
        cpasync16(b_ + 0 * STG_T + dOff + 16, gAh + kb_ + 16, szA);         \
        cpasync16(b_ + 1 * STG_T + dOff,      gAl + kb_,      szA);         \
        cpasync16(b_ + 1 * STG_T + dOff + 16, gAl + kb_ + 16, szA);         \
        cpasync16(b_ + 2 * STG_T + dOff,      gBh + kb_,      16);          \
        cpasync16(b_ + 2 * STG_T + dOff + 16, gBh + kb_ + 16, 16);          \
        cpasync16(b_ + 3 * STG_T + dOff,      gBl + kb_,      16);          \
        cpasync16(b_ + 3 * STG_T + dOff + 16, gBl + kb_ + 16, 16);          \
    } while (0)

    const uint32_t a_mr = (lane & 7) + ((lane >> 3) & 1) * 8;
    const uint32_t a_kc = (lane >> 4) * 8;
    const uint32_t b_nr = ((lane >> 4) & 1) * 8 + (lane & 7);
    const uint32_t b_kc = ((lane >> 3) & 1) * 8;

    const int nst = K >> 5;
    LOAD_STAGE(0, 0);
    CP_COMMIT;
    for (int s = 0; s < nst; s++) {
        if (s + 1 < nst) { LOAD_STAGE(s + 1, (s + 1) << 5); CP_COMMIT; CP_WAIT1; }
        else             { CP_WAIT0; }
        __syncthreads();

        uint32_t base = sb + (uint32_t)(s & 1) * STG_ALL;
        #pragma unroll
        for (int ksub = 0; ksub < 2; ksub++) {
            uint32_t ko = ksub * 32;
            uint32_t ah[2][4], al[2][4];
            #pragma unroll
            for (int mt = 0; mt < 2; mt++) {
                uint32_t aaddr = (uint32_t)((wm * 32 + mt * 16 + a_mr) * 80) + ko + a_kc * 2;
                LDSM4(ah[mt][0], ah[mt][1], ah[mt][2], ah[mt][3], base + 0 * STG_T + aaddr);
                LDSM4(al[mt][0], al[mt][1], al[mt][2], al[mt][3], base + 1 * STG_T + aaddr);
            }
            #pragma unroll
            for (int bg = 0; bg < 4; bg++) {
                uint32_t baddr = (uint32_t)((wn * 64 + bg * 16 + b_nr) * 80) + ko + b_kc * 2;
                uint32_t bh0, bh1, bh2, bh3, bl0, bl1, bl2, bl3;
                LDSM4(bh0, bh1, bh2, bh3, base + 2 * STG_T + baddr);
                LDSM4(bl0, bl1, bl2, bl3, base + 3 * STG_T + baddr);
                #pragma unroll
                for (int mt = 0; mt < 2; mt++) {
                    float* c0 = c[mt][bg * 2];
                    float* c1 = c[mt][bg * 2 + 1];
                    MMA16816(c0, ah[mt][0], ah[mt][1], ah[mt][2], ah[mt][3], bh0, bh1);
                    MMA16816(c0, ah[mt][0], ah[mt][1], ah[mt][2], ah[mt][3], bl0, bl1);
                    MMA16816(c0, al[mt][0], al[mt][1], al[mt][2], al[mt][3], bh0, bh1);
                    MMA16816(c1, ah[mt][0], ah[mt][1], ah[mt][2], ah[mt][3], bh2, bh3);
                    MMA16816(c1, ah[mt][0], ah[mt][1], ah[mt][2], ah[mt][3], bl2, bl3);
                    MMA16816(c1, al[mt][0], al[mt][1], al[mt][2], al[mt][3], bh2, bh3);
                }
            }
        }
        __syncthreads();
    }
#undef LOAD_STAGE

    const int rbase = bm + wm * 32 + (lane >> 2);
    const int cbase = bn + wn * 64 + (lane & 3) * 2;
    #pragma unroll
    for (int mt = 0; mt < 2; mt++) {
        #pragma unroll
        for (int nt = 0; nt < 8; nt++) {
            int rr = rbase + mt * 16;
            int cc = cbase + nt * 8;
            if (rr < M)
                *(float2*)&C[(size_t)rr * N + cc] = make_float2(c[mt][nt][0], c[mt][nt][1]);
            if (rr + 8 < M)
                *(float2*)&C[(size_t)(rr + 8) * N + cc] = make_float2(c[mt][nt][2], c[mt][nt][3]);
        }
    }
}

// ---------------- fused GATv2 layer 1 (H=10, C=64), warp per node ----------
// ab rows: [xl(640) | xr(640)], stride XSTR. Indices lane-preloaded per chunk.
__global__ void k_gat1_fused(const float* __restrict__ ab,
                             const int* __restrict__ rowptr,
                             const int* __restrict__ csr_src,
                             const float* __restrict__ att,
                             const float* __restrict__ bias,
                             __nv_bfloat16* __restrict__ ohi,
                             __nv_bfloat16* __restrict__ olo)
{
    int n = (blockIdx.x * blockDim.x + threadIdx.x) >> 5;
    int lane = threadIdx.x & 31;
    if (n >= NNODES) return;
    int r0 = rowptr[n], r1 = rowptr[n + 1];
    int k16 = lane & 15;

    float4 xr4[5], at4[5];
    const float4* pr = (const float4*)(ab + (size_t)n * XSTR + HID);
    const float4* pa = (const float4*)att;
    #pragma unroll
    for (int j = 0; j < 5; j++) {
        xr4[j] = pr[j * 32 + lane];
        at4[j] = pa[j * 32 + lane];
    }

    float m[5], den[5], acc[5][4];
    #pragma unroll
    for (int j = 0; j < 5; j++) {
        m[j] = -3.4e38f; den[j] = 0.f;
        acc[j][0] = acc[j][1] = acc[j][2] = acc[j][3] = 0.f;
    }

    for (int cs = r0; cs < r1; cs += 16) {
        int ce = min(cs + 16, r1);
        // lane-parallel index preload (one coalesced LDG per chunk)
        int sidx = (cs + k16 < r1) ? csr_src[cs + k16] : 0;
        float logreg[5];
        float cmax[5];
        #pragma unroll
        for (int j = 0; j < 5; j++) cmax[j] = -3.4e38f;

        for (int i = cs; i < ce; i++) {
            int s = __shfl_sync(0xffffffffu, sidx, i - cs);
            const float4* ps = (const float4*)(ab + (size_t)s * XSTR);
            float part[5];
            #pragma unroll
            for (int j = 0; j < 5; j++) {
                float4 x4 = ps[j * 32 + lane];
                float v, sum = 0.f;
                v = x4.x + xr4[j].x; v = v > 0.f ? v : NEGSLOPE * v; sum += v * at4[j].x;
                v = x4.y + xr4[j].y; v = v > 0.f ? v : NEGSLOPE * v; sum += v * at4[j].y;
                v = x4.z + xr4[j].z; v = v > 0.f ? v : NEGSLOPE * v; sum += v * at4[j].z;
                v = x4.w + xr4[j].w; v = v > 0.f ? v : NEGSLOPE * v; sum += v * at4[j].w;
                part[j] = sum;
            }
            #pragma unroll
            for (int o = 8; o > 0; o >>= 1) {
                #pragma unroll
                for (int j = 0; j < 5; j++)
                    part[j] += __shfl_xor_sync(0xffffffffu, part[j], o);
            }
            int k = i - cs;
            #pragma unroll
            for (int j = 0; j < 5; j++) {
                if (k16 == k) logreg[j] = part[j];
                cmax[j] = fmaxf(cmax[j], part[j]);
            }
        }
        #pragma unroll
        for (int j = 0; j < 5; j++) {
            float nm = fmaxf(m[j], cmax[j]);
            float sc = expf(m[j] - nm);
            den[j] *= sc;
            acc[j][0] *= sc; acc[j][1] *= sc; acc[j][2] *= sc; acc[j][3] *= sc;
            m[j] = nm;
        }
        for (int i = cs; i < ce; i++) {
            int s = __shfl_sync(0xffffffffu, sidx, i - cs);
            const float4* ps = (const float4*)(ab + (size_t)s * XSTR);
            int srcl = (lane & 16) | (i - cs);
            #pragma unroll
            for (int j = 0; j < 5; j++) {
                float lg = __shfl_sync(0xffffffffu, logreg[j], srcl);
                float ex = expf(lg - m[j]);
                den[j] += ex;
                float4 x4 = ps[j * 32 + lane];
                acc[j][0] += ex * x4.x;
                acc[j][1] += ex * x4.y;
                acc[j][2] += ex * x4.z;
                acc[j][3] += ex * x4.w;
            }
        }
    }
    #pragma unroll
    for (int j = 0; j < 5; j++) {
        float inv = 1.f / den[j];
        int cb = (j * 32 + lane) * 4;
        float o0 = acc[j][0] * inv + bias[cb];
        float o1 = acc[j][1] * inv + bias[cb + 1];
        float o2 = acc[j][2] * inv + bias[cb + 2];
        float o3 = acc[j][3] * inv + bias[cb + 3];
        o0 = o0 > 0.f ? o0 : expm1f(o0);
        o1 = o1 > 0.f ? o1 : expm1f(o1);
        o2 = o2 > 0.f ? o2 : expm1f(o2);
        o3 = o3 > 0.f ? o3 : expm1f(o3);
        __nv_bfloat16 h0 = __float2bfloat16(o0), h1 = __float2bfloat16(o1);
        __nv_bfloat16 h2 = __float2bfloat16(o2), h3 = __float2bfloat16(o3);
        __nv_bfloat162 hp0; hp0.x = h0; hp0.y = h1;
        __nv_bfloat162 hp1; hp1.x = h2; hp1.y = h3;
        __nv_bfloat162 lp0, lp1;
        lp0.x = __float2bfloat16(o0 - __bfloat162float(h0));
        lp0.y = __float2bfloat16(o1 - __bfloat162float(h1));
        lp1.x = __float2bfloat16(o2 - __bfloat162float(h2));
        lp1.y = __float2bfloat16(o3 - __bfloat162float(h3));
        *(__nv_bfloat162*)&ohi[(size_t)n * HID + cb]     = hp0;
        *(__nv_bfloat162*)&ohi[(size_t)n * HID + cb + 2] = hp1;
        *(__nv_bfloat162*)&olo[(size_t)n * HID + cb]     = lp0;
        *(__nv_bfloat162*)&olo[(size_t)n * HID + cb + 2] = lp1;
    }
}

// ---------------- fused GATv2 layer 2 (H=1, C=640), warp per node ----------
__global__ void k_gat2_fused(const float* __restrict__ ab,
                             const int* __restrict__ rowptr,
                             const int* __restrict__ csr_src,
                             const float* __restrict__ att,
                             const float* __restrict__ bias,
                             __nv_bfloat16* __restrict__ ohi,
                             __nv_bfloat16* __restrict__ olo)
{
    int n = (blockIdx.x * blockDim.x + threadIdx.x) >> 5;
    int lane = threadIdx.x & 31;
    if (n >= NNODES) return;
    int r0 = rowptr[n], r1 = rowptr[n + 1];

    float4 xr4[5], at4[5];
    const float4* pr = (const float4*)(ab + (size_t)n * XSTR + HID);
    const float4* pa = (const float4*)att;
    #pragma unroll
    for (int j = 0; j < 5; j++) {
        xr4[j] = pr[j * 32 + lane];
        at4[j] = pa[j * 32 + lane];
    }

    float m = -3.4e38f, den = 0.f;
    float acc[5][4];
    #pragma unroll
    for (int j = 0; j < 5; j++)
        #pragma unroll
        for (int q = 0; q < 4; q++) acc[j][q] = 0.f;

    for (int cs = r0; cs < r1; cs += 32) {
        int ce = min(cs + 32, r1);
        int sidx = (cs + lane < r1) ? csr_src[cs + lane] : 0;
        float logreg;
        float cmax = -3.4e38f;
        for (int i = cs; i < ce; i++) {
            int s = __shfl_sync(0xffffffffu, sidx, i - cs);
            const float4* ps = (const float4*)(ab + (size_t)s * XSTR);
            float sum = 0.f;
            #pragma unroll
            for (int j = 0; j < 5; j++) {
                float4 x4 = ps[j * 32 + lane];
                float v;
                v = x4.x + xr4[j].x; v = v > 0.f ? v : NEGSLOPE * v; sum += v * at4[j].x;
                v = x4.y + xr4[j].y; v = v > 0.f ? v : NEGSLOPE * v; sum += v * at4[j].y;
                v = x4.z + xr4[j].z; v = v > 0.f ? v : NEGSLOPE * v; sum += v * at4[j].z;
                v = x4.w + xr4[j].w; v = v > 0.f ? v : NEGSLOPE * v; sum += v * at4[j].w;
            }
            #pragma unroll
            for (int o = 16; o > 0; o >>= 1)
                sum += __shfl_xor_sync(0xffffffffu, sum, o);
            if (lane == i - cs) logreg = sum;
            cmax = fmaxf(cmax, sum);
        }
        float nm = fmaxf(m, cmax);
        float sc = expf(m - nm);
        den *= sc;
        #pragma unroll
        for (int j = 0; j < 5; j++) {
            acc[j][0] *= sc; acc[j][1] *= sc; acc[j][2] *= sc; acc[j][3] *= sc;
        }
        m = nm;
        for (int i = cs; i < ce; i++) {
            int s = __shfl_sync(0xffffffffu, sidx, i - cs);
            const float4* ps = (const float4*)(ab + (size_t)s * XSTR);
            float lg = __shfl_sync(0xffffffffu, logreg, i - cs);
            float ex = expf(lg - m);
            den += ex;
            #pragma unroll
            for (int j = 0; j < 5; j++) {
                float4 x4 = ps[j * 32 + lane];
                acc[j][0] += ex * x4.x;
                acc[j][1] += ex * x4.y;
                acc[j][2] += ex * x4.z;
                acc[j][3] += ex * x4.w;
            }
        }
    }
    float inv = 1.f / den;
    #pragma unroll
    for (int j = 0; j < 5; j++) {
        int cb = (j * 32 + lane) * 4;
        float o0 = acc[j][0] * inv + bias[cb];
        float o1 = acc[j][1] * inv + bias[cb + 1];
        float o2 = acc[j][2] * inv + bias[cb + 2];
        float o3 = acc[j][3] * inv + bias[cb + 3];
        __nv_bfloat16 h0 = __float2bfloat16(o0), h1 = __float2bfloat16(o1);
        __nv_bfloat16 h2 = __float2bfloat16(o2), h3 = __float2bfloat16(o3);
        __nv_bfloat162 hp0; hp0.x = h0; hp0.y = h1;
        __nv_bfloat162 hp1; hp1.x = h2; hp1.y = h3;
        __nv_bfloat162 lp0, lp1;
        lp0.x = __float2bfloat16(o0 - __bfloat162float(h0));
        lp0.y = __float2bfloat16(o1 - __bfloat162float(h1));
        lp1.x = __float2bfloat16(o2 - __bfloat162float(h2));
        lp1.y = __float2bfloat16(o3 - __bfloat162float(h3));
        *(__nv_bfloat162*)&ohi[(size_t)n * HID + cb]     = hp0;
        *(__nv_bfloat162*)&ohi[(size_t)n * HID + cb + 2] = hp1;
        *(__nv_bfloat162*)&olo[(size_t)n * HID + cb]     = lp0;
        *(__nv_bfloat162*)&olo[(size_t)n * HID + cb + 2] = lp1;
    }
}

// ---------------- GCN node aggregate + relu + fused pooling + cnt ----------
__global__ void k_gcn_node(const float* __restrict__ xw,
                           const int* __restrict__ rowptr,
                           const int* __restrict__ csr_src,
                           const float* __restrict__ dinv,
                           const float* __restrict__ bg,
                           const int* __restrict__ batch,
                           int* __restrict__ gmax, float* __restrict__ gsum,
                           float* __restrict__ cnt)
{
    int n = (blockIdx.x * blockDim.x + threadIdx.x) >> 5;
    int lane = threadIdx.x & 31;
    if (n >= NNODES) return;
    int r0 = rowptr[n], r1 = rowptr[n + 1];
    int g = batch[n];           // hoisted early
    float dv = dinv[n];

    float acc[5][4];
    #pragma unroll
    for (int j = 0; j < 5; j++)
        #pragma unroll
        for (int q = 0; q < 4; q++) acc[j][q] = 0.f;

    for (int cs = r0; cs < r1; cs += 32) {
        int ce = min(cs + 32, r1);
        bool valid = (cs + lane < r1);
        int   sidx = valid ? csr_src[cs + lane] : 0;
        float dsl  = valid ? dinv[sidx] : 0.f;     // lane-parallel dinv gather
        for (int i = cs; i < ce; i++) {
            int   s   = __shfl_sync(0xffffffffu, sidx, i - cs);
            float nrm = __shfl_sync(0xffffffffu, dsl,  i - cs) * dv;
            const float4* ps = (const float4*)(xw + (size_t)s * HID);
            #pragma unroll
            for (int j = 0; j < 5; j++) {
                float4 v = ps[j * 32 + lane];
                acc[j][0] += nrm * v.x;
                acc[j][1] += nrm * v.y;
                acc[j][2] += nrm * v.z;
                acc[j][3] += nrm * v.w;
            }
        }
    }
    if (lane == 0) atomicAdd(&cnt[g], 1.f);
    #pragma unroll
    for (int j = 0; j < 5; j++) {
        int cb = (j * 32 + lane) * 4;
        #pragma unroll
        for (int q = 0; q < 4; q++) {
            float o = fmaxf(acc[j][q] + bg[cb + q], 0.f);
            atomicMax(&gmax[g * HID + cb + q], __float_as_int(o));
            atomicAdd(&gsum[g * HID + cb + q], o);
        }
    }
}

// ---------------- pooling tail ---------------------------------------------
__global__ void k_final(const int* __restrict__ gmax, const float* __restrict__ gsum,
                        const float* __restrict__ cnt, float* __restrict__ out)
{
    int idx = blockIdx.x * blockDim.x + threadIdx.x;
    if (idx >= NGRAPH * HID) return;
    int g = idx / HID, c = idx % HID;
    out[(size_t)g * (2 * HID) + c]       = __int_as_float(gmax[idx]);
    out[(size_t)g * (2 * HID) + HID + c] = gsum[idx] / fmaxf(cnt[g], 1.f);
}

// ---------------- launch ---------------------------------------------------
extern "C" void kernel_launch(void* const* d_in, const int* in_sizes, int n_in,
                              void* d_out, int out_size)
{
    const float* x     = (const float*)d_in[0];
    const int*   ei    = (const int*)d_in[1];
    const int*   batch = (const int*)d_in[2];
    const float* Wl1 = (const float*)d_in[3];
    const float* Wr1 = (const float*)d_in[4];
    const float* a1  = (const float*)d_in[5];
    const float* b1  = (const float*)d_in[6];
    const float* Wl2 = (const float*)d_in[7];
    const float* Wr2 = (const float*)d_in[8];
    const float* a2  = (const float*)d_in[9];
    const float* b2  = (const float*)d_in[10];
    const float* Wg  = (const float*)d_in[11];
    const float* bg  = (const float*)d_in[12];
    float* out = (float*)d_out;

    float *AB, *dinv, *gsum, *cnt;
    int *rowptr, *cntbuf, *csr_src, *gmax;
    __nv_bfloat16 *xhi, *xlo, *hhi, *hlo;
    __nv_bfloat16 *w1hi, *w1lo, *w2hi, *w2lo, *wghi, *wglo;
    cudaGetSymbolAddress((void**)&AB,      g_bufAB);
    cudaGetSymbolAddress((void**)&dinv,    g_dinv);
    cudaGetSymbolAddress((void**)&rowptr,  g_rowptr);
    cudaGetSymbolAddress((void**)&cntbuf,  g_cntbuf);
    cudaGetSymbolAddress((void**)&csr_src, g_csr_src);
    cudaGetSymbolAddress((void**)&gmax,    g_gmax);
    cudaGetSymbolAddress((void**)&gsum,    g_gsum);
    cudaGetSymbolAddress((void**)&cnt,     g_cnt);
    cudaGetSymbolAddress((void**)&xhi,     g_xhi);
    cudaGetSymbolAddress((void**)&xlo,     g_xlo);
    cudaGetSymbolAddress((void**)&hhi,     g_hhi);
    cudaGetSymbolAddress((void**)&hlo,     g_hlo);
    cudaGetSymbolAddress((void**)&w1hi,    g_w1hi);
    cudaGetSymbolAddress((void**)&w1lo,    g_w1lo);
    cudaGetSymbolAddress((void**)&w2hi,    g_w2hi);
    cudaGetSymbolAddress((void**)&w2lo,    g_w2lo);
    cudaGetSymbolAddress((void**)&wghi,    g_wghi);
    cudaGetSymbolAddress((void**)&wglo,    g_wglo);

    // one-time infra (created on the uncaptured correctness call)
    static cudaStream_t s2 = nullptr;
    static cudaEvent_t evFork = nullptr, evJoin = nullptr;
    static bool attr_set = false;
    if (!attr_set) {
        cudaFuncSetAttribute(k_hgemm, cudaFuncAttributeMaxDynamicSharedMemorySize, 2 * STG_ALL);
        cudaStreamCreateWithFlags(&s2, cudaStreamNonBlocking);
        cudaEventCreateWithFlags(&evFork, cudaEventDisableTiming);
        cudaEventCreateWithFlags(&evJoin, cudaEventDisableTiming);
        attr_set = true;
    }

    const int T = 256;
    dim3 gg2(2 * HID / 128, (NNODES + 127) / 128);       // (10, 391) concat
    dim3 gg1(HID / 128, (NNODES + 127) / 128);           // (5, 391)
    int nb   = (NNODES + T - 1) / T;
    int n2b  = (2 * NNODES + T - 1) / T;
    int epb  = (EPLUS + T - 1) / T;
    int ghb  = (NGRAPH * HID + T - 1) / T;
    int xsb  = (NNODES * KP1 + T - 1) / T;
    int w1b  = (HID * KP1 + T - 1) / T;
    int w2b  = (HID * HID + T - 1) / T;
    int nwN  = (NNODES * 32 + T - 1) / T;                // warp per node

    // ---- main stream: layer-1 prep ----
    k_split <<<xsb, T>>>(x, xhi, xlo, NNODES, INDIM, KP1);
    k_splitT<<<w1b, T>>>(Wl1, w1hi, w1lo, INDIM, HID, KP1);
    k_splitT<<<w1b, T>>>(Wr1, w1hi + (size_t)HID * KP1, w1lo + (size_t)HID * KP1,
                         INDIM, HID, KP1);

    // ---- fork: CSR build + layer-2/3 weight splits + pool init on s2 ----
    cudaEventRecord(evFork, 0);
    cudaStreamWaitEvent(s2, evFork, 0);
    k_fill_i <<<n2b, T, 0, s2>>>(cntbuf, 0, 2 * NNODES);
    k_count  <<<epb, T, 0, s2>>>(ei, cntbuf);
    k_scan   <<<1, 1024, 0, s2>>>(cntbuf, rowptr);
    k_scatter<<<epb, T, 0, s2>>>(ei, rowptr, cntbuf + NNODES, csr_src);
    k_dinv   <<<nb, T, 0, s2>>>(rowptr, dinv);
    k_splitT <<<w2b, T, 0, s2>>>(Wl2, w2hi, w2lo, HID, HID, HID);
    k_splitT <<<w2b, T, 0, s2>>>(Wr2, w2hi + (size_t)HID * HID, w2lo + (size_t)HID * HID,
                                 HID, HID, HID);
    k_splitT <<<w2b, T, 0, s2>>>(Wg, wghi, wglo, HID, HID, HID);
    k_pool_init<<<ghb, T, 0, s2>>>(gmax, gsum, cnt);
    cudaEventRecord(evJoin, s2);

    // ---- Layer 1: concat GEMM (xl|xr), then fused GATv2 ----
    k_hgemm<<<gg2, T, 2 * STG_ALL>>>(xhi, xlo, w1hi, w1lo, AB, NNODES, XSTR, KP1);
    cudaStreamWaitEvent(0, evJoin, 0);
    k_gat1_fused<<<nwN, T>>>(AB, rowptr, csr_src, a1, b1, hhi, hlo);

    // ---- Layer 2: concat GEMM, fused GATv2 ----
    k_hgemm<<<gg2, T, 2 * STG_ALL>>>(hhi, hlo, w2hi, w2lo, AB, NNODES, XSTR, HID);
    k_gat2_fused<<<nwN, T>>>(AB, rowptr, csr_src, a2, b2, hhi, hlo);

    // ---- Layer 3: GCN + relu + fused pooling ----
    k_hgemm<<<gg1, T, 2 * STG_ALL>>>(hhi, hlo, wghi, wglo, AB, NNODES, HID, HID);
    k_gcn_node<<<nwN, T>>>(AB, rowptr, csr_src, dinv, bg, batch, gmax, gsum, cnt);
    k_final<<<ghb, T>>>(gmax, gsum, cnt, out);
}